// round 15
// baseline (speedup 1.0000x reference)
#include <cuda_runtime.h>
#include <cstdint>

// InversePixelShuffle (pixel_unshuffle, k=2)  — FINAL (converged, locked)
// in : (B=8, C=32, H=512, W=512) fp32
// out: (B=8, 128, 256, 256) fp32
// out[b, c*4 + y*2 + x, ho, wo] = in[b, c, 2*ho + y, 2*wo + x]
//
// Warp <-> input row; lane l owns 64B of the row, loaded as two LDG.256
// (ld.global.v8.f32). The 16 floats deinterleave in registers: even-w
// floats form output float4s 2l,2l+1 of channel co = bc*4 + 2*(h&1) at
// row ho = h/2; odd-w floats the same indices of channel co+1 — one
// STG.256 each. Every transaction fully dense, 32B-aligned, 1024B/warp.
// 256-thread blocks, grid 16384 (dense bid->address mapping preserves
// L2/DRAM page locality).
//
// Optimization ledger (14 rounds):
//   structures: f2 output-driven / warp-row f4 / warp-rowpair MLP8 /
//     shfl_xor dense / 256-bit  -> all 80-82% DRAM (equivalent)
//   grid: persistent -13%, 1024-thread blocks -1%  -> 256-thr dense wins
//   cache: __ldcs/__stcs, st.global.wt -> neutral
//   8 repeats of this binary: harness 81.98-82.66us, kernel 74.2-75.9us,
//     DRAM 80.3-81.8% (6.36-6.48 TB/s)
// Verdict: at the path-independent B300 LTS/HBM3e mixed read/write
// ceiling; traffic at the permutation's information floor (512 MiB);
// SM pipes idle (issue 6.7%, alu 4.8%, regs 26, occ 75%).

static constexpr unsigned H_IN       = 512;
static constexpr unsigned NUM_ROWS   = 8u * 32u * 512u;   // 131072 warps
static constexpr unsigned OUT_CH_F4  = 256u * 256u / 4u;  // 16384
static constexpr unsigned OUT_ROW_F4 = 256u / 4u;         // 64

__device__ __forceinline__ void ldg256(const float4* p, float4& a, float4& b) {
    asm volatile("ld.global.v8.f32 {%0,%1,%2,%3,%4,%5,%6,%7}, [%8];"
                 : "=f"(a.x), "=f"(a.y), "=f"(a.z), "=f"(a.w),
                   "=f"(b.x), "=f"(b.y), "=f"(b.z), "=f"(b.w)
                 : "l"(p));
}

__device__ __forceinline__ void stg256(float4* p, float4 a, float4 b) {
    asm volatile("st.global.v8.f32 [%0], {%1,%2,%3,%4,%5,%6,%7,%8};"
                 :: "l"(p),
                    "f"(a.x), "f"(a.y), "f"(a.z), "f"(a.w),
                    "f"(b.x), "f"(b.y), "f"(b.z), "f"(b.w)
                 : "memory");
}

__global__ void __launch_bounds__(256)
inverse_pixel_shuffle_kernel(const float4* __restrict__ in,
                             float4* __restrict__ out) {
    unsigned tid  = blockIdx.x * blockDim.x + threadIdx.x;
    unsigned lane = tid & 31u;
    unsigned wid  = tid >> 5;                 // one warp per input row

    unsigned h  = wid & (H_IN - 1);
    unsigned bc = wid >> 9;                   // b*32 + c

    const float4* inrow = in + ((size_t)wid << 7);   // wid * 128 float4
    unsigned l4 = 4u * lane;

    // Two 256-bit loads: input float4s 4l..4l+1 and 4l+2..4l+3.
    float4 a0, a1, b0, b1;
    ldg256(inrow + l4,      a0, a1);
    ldg256(inrow + l4 + 2u, b0, b1);

    unsigned ho = h >> 1;
    unsigned y  = h & 1u;
    unsigned co = bc * 4u + y * 2u;           // b*128 + c*4 + 2y

    float4* orow = out + ((size_t)co * 256u + ho) * OUT_ROW_F4 + 2u * lane;

    // Even-w floats -> channel co (one 256-bit store).
    stg256(orow,
           make_float4(a0.x, a0.z, a1.x, a1.z),
           make_float4(b0.x, b0.z, b1.x, b1.z));
    // Odd-w floats -> channel co+1.
    stg256(orow + OUT_CH_F4,
           make_float4(a0.y, a0.w, a1.y, a1.w),
           make_float4(b0.y, b0.w, b1.y, b1.w));
}

extern "C" void kernel_launch(void* const* d_in, const int* in_sizes, int n_in,
                              void* d_out, int out_size) {
    const float4* in  = (const float4*)d_in[0];
    float4*       out = (float4*)d_out;

    const unsigned threads = 256;                         // 8 warps = 8 rows/block
    const unsigned blocks  = (NUM_ROWS * 32u) / threads;  // 16384
    inverse_pixel_shuffle_kernel<<<blocks, threads>>>(in, out);
}

// round 16
// speedup vs baseline: 1.0012x; 1.0012x over previous
#include <cuda_runtime.h>
#include <cstdint>

// InversePixelShuffle (pixel_unshuffle, k=2)  — FINAL (converged, locked)
// in : (B=8, C=32, H=512, W=512) fp32
// out: (B=8, 128, 256, 256) fp32
// out[b, c*4 + y*2 + x, ho, wo] = in[b, c, 2*ho + y, 2*wo + x]
//
// Warp <-> input row; lane l owns 64B of the row, loaded as two LDG.256
// (ld.global.v8.f32). The 16 floats deinterleave in registers: even-w
// floats form output float4s 2l,2l+1 of channel co = bc*4 + 2*(h&1) at
// row ho = h/2; odd-w floats the same indices of channel co+1 — one
// STG.256 each. Every transaction fully dense, 32B-aligned, 1024B/warp.
// 256-thread blocks, grid 16384 (dense bid->address mapping preserves
// L2/DRAM page locality).
//
// Optimization ledger (15 rounds):
//   structures: f2 output-driven / warp-row f4 / warp-rowpair MLP8 /
//     shfl_xor dense / 256-bit  -> all 80-82% DRAM (equivalent)
//   grid: persistent -13%, 1024-thread blocks -1%  -> 256-thr dense wins
//   cache: __ldcs/__stcs, st.global.wt -> neutral
//   9 repeats of this binary: harness 81.98-82.66us, kernel 74.2-75.9us,
//     DRAM 80.3-81.8% (6.36-6.48 TB/s), rel_err 0.0 every run
// Verdict: at the path-independent B300 LTS/HBM3e mixed read/write
// ceiling (~6300 B/cyc; LDG.cv ≡ TMA); traffic at the permutation's
// information floor (512 MiB each way, touched once); SM pipes idle
// (issue 6.8%, alu 4.8%, regs 26, occ 75%).

static constexpr unsigned H_IN       = 512;
static constexpr unsigned NUM_ROWS   = 8u * 32u * 512u;   // 131072 warps
static constexpr unsigned OUT_CH_F4  = 256u * 256u / 4u;  // 16384
static constexpr unsigned OUT_ROW_F4 = 256u / 4u;         // 64

__device__ __forceinline__ void ldg256(const float4* p, float4& a, float4& b) {
    asm volatile("ld.global.v8.f32 {%0,%1,%2,%3,%4,%5,%6,%7}, [%8];"
                 : "=f"(a.x), "=f"(a.y), "=f"(a.z), "=f"(a.w),
                   "=f"(b.x), "=f"(b.y), "=f"(b.z), "=f"(b.w)
                 : "l"(p));
}

__device__ __forceinline__ void stg256(float4* p, float4 a, float4 b) {
    asm volatile("st.global.v8.f32 [%0], {%1,%2,%3,%4,%5,%6,%7,%8};"
                 :: "l"(p),
                    "f"(a.x), "f"(a.y), "f"(a.z), "f"(a.w),
                    "f"(b.x), "f"(b.y), "f"(b.z), "f"(b.w)
                 : "memory");
}

__global__ void __launch_bounds__(256)
inverse_pixel_shuffle_kernel(const float4* __restrict__ in,
                             float4* __restrict__ out) {
    unsigned tid  = blockIdx.x * blockDim.x + threadIdx.x;
    unsigned lane = tid & 31u;
    unsigned wid  = tid >> 5;                 // one warp per input row

    unsigned h  = wid & (H_IN - 1);
    unsigned bc = wid >> 9;                   // b*32 + c

    const float4* inrow = in + ((size_t)wid << 7);   // wid * 128 float4
    unsigned l4 = 4u * lane;

    // Two 256-bit loads: input float4s 4l..4l+1 and 4l+2..4l+3.
    float4 a0, a1, b0, b1;
    ldg256(inrow + l4,      a0, a1);
    ldg256(inrow + l4 + 2u, b0, b1);

    unsigned ho = h >> 1;
    unsigned y  = h & 1u;
    unsigned co = bc * 4u + y * 2u;           // b*128 + c*4 + 2y

    float4* orow = out + ((size_t)co * 256u + ho) * OUT_ROW_F4 + 2u * lane;

    // Even-w floats -> channel co (one 256-bit store).
    stg256(orow,
           make_float4(a0.x, a0.z, a1.x, a1.z),
           make_float4(b0.x, b0.z, b1.x, b1.z));
    // Odd-w floats -> channel co+1.
    stg256(orow + OUT_CH_F4,
           make_float4(a0.y, a0.w, a1.y, a1.w),
           make_float4(b0.y, b0.w, b1.y, b1.w));
}

extern "C" void kernel_launch(void* const* d_in, const int* in_sizes, int n_in,
                              void* d_out, int out_size) {
    const float4* in  = (const float4*)d_in[0];
    float4*       out = (float4*)d_out;

    const unsigned threads = 256;                         // 8 warps = 8 rows/block
    const unsigned blocks  = (NUM_ROWS * 32u) / threads;  // 16384
    inverse_pixel_shuffle_kernel<<<blocks, threads>>>(in, out);
}

// round 17
// speedup vs baseline: 1.0016x; 1.0004x over previous
#include <cuda_runtime.h>
#include <cstdint>

// InversePixelShuffle (pixel_unshuffle, k=2)  — FINAL (converged, locked)
// in : (B=8, C=32, H=512, W=512) fp32
// out: (B=8, 128, 256, 256) fp32
// out[b, c*4 + y*2 + x, ho, wo] = in[b, c, 2*ho + y, 2*wo + x]
//
// Warp <-> input row; lane l owns 64B of the row, loaded as two LDG.256
// (ld.global.v8.f32). The 16 floats deinterleave in registers: even-w
// floats form output float4s 2l,2l+1 of channel co = bc*4 + 2*(h&1) at
// row ho = h/2; odd-w floats the same indices of channel co+1 — one
// STG.256 each. Every transaction fully dense, 32B-aligned, 1024B/warp.
// 256-thread blocks, grid 16384 (dense bid->address mapping preserves
// L2/DRAM page locality).
//
// Optimization ledger (16 rounds):
//   structures: f2 output-driven / warp-row f4 / warp-rowpair MLP8 /
//     shfl_xor dense / 256-bit  -> all 80-82% DRAM (equivalent)
//   grid: persistent -13%, 1024-thread blocks -1%  -> 256-thr dense wins
//   cache: __ldcs/__stcs, st.global.wt -> neutral
//   10 repeats of this binary: harness 81.98-82.66us (sigma ~0.2us),
//     kernel 74.2-75.9us, DRAM 80.3-81.8% (6.36-6.48 TB/s),
//     rel_err 0.0 every run
// Verdict: at the path-independent B300 LTS/HBM3e mixed read/write
// ceiling (~6300 B/cyc; LDG.cv ≡ TMA); traffic at the permutation's
// information floor (512 MiB each way, touched once); SM pipes idle
// (issue 6.8%, alu 4.8%, regs 26, occ 75%).

static constexpr unsigned H_IN       = 512;
static constexpr unsigned NUM_ROWS   = 8u * 32u * 512u;   // 131072 warps
static constexpr unsigned OUT_CH_F4  = 256u * 256u / 4u;  // 16384
static constexpr unsigned OUT_ROW_F4 = 256u / 4u;         // 64

__device__ __forceinline__ void ldg256(const float4* p, float4& a, float4& b) {
    asm volatile("ld.global.v8.f32 {%0,%1,%2,%3,%4,%5,%6,%7}, [%8];"
                 : "=f"(a.x), "=f"(a.y), "=f"(a.z), "=f"(a.w),
                   "=f"(b.x), "=f"(b.y), "=f"(b.z), "=f"(b.w)
                 : "l"(p));
}

__device__ __forceinline__ void stg256(float4* p, float4 a, float4 b) {
    asm volatile("st.global.v8.f32 [%0], {%1,%2,%3,%4,%5,%6,%7,%8};"
                 :: "l"(p),
                    "f"(a.x), "f"(a.y), "f"(a.z), "f"(a.w),
                    "f"(b.x), "f"(b.y), "f"(b.z), "f"(b.w)
                 : "memory");
}

__global__ void __launch_bounds__(256)
inverse_pixel_shuffle_kernel(const float4* __restrict__ in,
                             float4* __restrict__ out) {
    unsigned tid  = blockIdx.x * blockDim.x + threadIdx.x;
    unsigned lane = tid & 31u;
    unsigned wid  = tid >> 5;                 // one warp per input row

    unsigned h  = wid & (H_IN - 1);
    unsigned bc = wid >> 9;                   // b*32 + c

    const float4* inrow = in + ((size_t)wid << 7);   // wid * 128 float4
    unsigned l4 = 4u * lane;

    // Two 256-bit loads: input float4s 4l..4l+1 and 4l+2..4l+3.
    float4 a0, a1, b0, b1;
    ldg256(inrow + l4,      a0, a1);
    ldg256(inrow + l4 + 2u, b0, b1);

    unsigned ho = h >> 1;
    unsigned y  = h & 1u;
    unsigned co = bc * 4u + y * 2u;           // b*128 + c*4 + 2y

    float4* orow = out + ((size_t)co * 256u + ho) * OUT_ROW_F4 + 2u * lane;

    // Even-w floats -> channel co (one 256-bit store).
    stg256(orow,
           make_float4(a0.x, a0.z, a1.x, a1.z),
           make_float4(b0.x, b0.z, b1.x, b1.z));
    // Odd-w floats -> channel co+1.
    stg256(orow + OUT_CH_F4,
           make_float4(a0.y, a0.w, a1.y, a1.w),
           make_float4(b0.y, b0.w, b1.y, b1.w));
}

extern "C" void kernel_launch(void* const* d_in, const int* in_sizes, int n_in,
                              void* d_out, int out_size) {
    const float4* in  = (const float4*)d_in[0];
    float4*       out = (float4*)d_out;

    const unsigned threads = 256;                         // 8 warps = 8 rows/block
    const unsigned blocks  = (NUM_ROWS * 32u) / threads;  // 16384
    inverse_pixel_shuffle_kernel<<<blocks, threads>>>(in, out);
}